// round 5
// baseline (speedup 1.0000x reference)
#include <cuda_runtime.h>
#include <cstdint>

// Problem shape (fixed by the reference)
#define T_STEPS 5
#define BB 32
#define CC 128
#define HW 1024                   // 32*32
#define NPLANES (BB * CC)         // 4096 (b,c) planes
#define NPT (NPLANES * HW)        // 4,194,304 elements per timestep

#define NBLK 1024                 // each block owns exactly 4 planes
#define PPB 4                     // planes per block (compile-time)

static constexpr float V_TH    = 0.5f;
static constexpr float W_DEC   = 0.5f;
static constexpr float LOWER_C = 0.2f - 0.03f;   // 0.17
static constexpr float UPPER_C = 0.2f + 0.03f;   // 0.23
static constexpr float EMA0    = 0.17f;
static constexpr float INV_N   = 1.0f / 32768.0f; // 1/(B*H*W)

// Cross-kernel state (device globals — no allocation allowed)
__device__ float g_mem[NPT];                 // membrane carry (L2-resident in practice)
__device__ float g_chsum[T_STEPS - 1][CC];   // per-step per-channel spike sums

__device__ __forceinline__ float sigmoidf(float x) {
    return 1.0f / (1.0f + expf(-x));
}

__global__ void lif_init() {
    int i = threadIdx.x + blockIdx.x * blockDim.x;
    if (i < (T_STEPS - 1) * CC) ((float*)g_chsum)[i] = 0.0f;
}

// One timestep. Block b owns planes [4b, 4b+4): 4 fully-unrolled iterations of
// 256 threads x float4 (one HW-plane each). EMA/inhw for the block's 4
// channels is recomputed in-kernel from the persisted per-step sums (the
// kernel boundary orders step t-1's atomics before step t's reads), which
// removes the separate EMA kernels from the graph.
template <int TI>
__global__ __launch_bounds__(256)
void lif_step(const float* __restrict__ xe,
              const float* __restrict__ xi,
              const float* __restrict__ alpha_raw,
              const float* __restrict__ beta_raw,
              float* __restrict__ out)
{
    constexpr bool FIRST = (TI == 0);
    constexpr bool LAST  = (TI == T_STEPS - 1);

    __shared__ float s_bw[PPB];     // beta*(1-inhw) per owned plane
    __shared__ float s_psum[PPB];   // per-plane spike sums

    const int tid  = threadIdx.x;
    const int lane = tid & 31;
    const float beta = sigmoidf(__ldg(beta_raw));

    if (tid < PPB) {
        float bw;
        if (FIRST) {
            bw = beta;                       // inhw starts at 0
        } else {
            const int c = (blockIdx.x * PPB + tid) & (CC - 1);
            float e = EMA0;
            #pragma unroll
            for (int k = 0; k < TI; ++k)
                e = 0.9f * e + 0.1f * (__ldcg(&g_chsum[k][c]) * INV_N);
            const float inhw = 4.0f * (sigmoidf(LOWER_C - e) - sigmoidf(e - UPPER_C));
            bw = beta * (1.0f - inhw);
        }
        s_bw[tid] = bw;
        s_psum[tid] = 0.0f;
    }
    const float alpha = 4.0f * sigmoidf(__ldg(alpha_raw));
    __syncthreads();

    const size_t blockBase = (size_t)blockIdx.x * (PPB * HW)
                           + (size_t)TI * NPT + (size_t)tid * 4;
    const size_t memBase   = (size_t)blockIdx.x * (PPB * HW) + (size_t)tid * 4;

    float cnt[PPB];

    #pragma unroll
    for (int j = 0; j < PPB; ++j) {
        const size_t idx = blockBase + (size_t)j * HW;
        const float4 e4 = __ldcs(reinterpret_cast<const float4*>(xe + idx));
        const float4 i4 = __ldcs(reinterpret_cast<const float4*>(xi + idx));
        float4 m;
        if (FIRST) m = make_float4(0.f, 0.f, 0.f, 0.f);
        else       m = __ldcg(reinterpret_cast<const float4*>(g_mem + memBase + (size_t)j * HW));
        const float bw = s_bw[j];
        float4 s;

        m.x = W_DEC * m.x + e4.x / (1.0f + alpha * i4.x) - bw * i4.x;
        s.x = (m.x >= V_TH) ? 1.0f : 0.0f;  m.x -= V_TH * s.x;
        m.y = W_DEC * m.y + e4.y / (1.0f + alpha * i4.y) - bw * i4.y;
        s.y = (m.y >= V_TH) ? 1.0f : 0.0f;  m.y -= V_TH * s.y;
        m.z = W_DEC * m.z + e4.z / (1.0f + alpha * i4.z) - bw * i4.z;
        s.z = (m.z >= V_TH) ? 1.0f : 0.0f;  m.z -= V_TH * s.z;
        m.w = W_DEC * m.w + e4.w / (1.0f + alpha * i4.w) - bw * i4.w;
        s.w = (m.w >= V_TH) ? 1.0f : 0.0f;  m.w -= V_TH * s.w;

        __stcs(reinterpret_cast<float4*>(out + idx), s);
        if (!LAST) {
            __stcg(reinterpret_cast<float4*>(g_mem + memBase + (size_t)j * HW), m);
            cnt[j] = s.x + s.y + s.z + s.w;
        }
    }

    if (!LAST) {
        // Per-plane spike sums: warp shuffle -> smem -> one global atomic each
        #pragma unroll
        for (int j = 0; j < PPB; ++j) {
            float v = cnt[j];
            #pragma unroll
            for (int off = 16; off > 0; off >>= 1)
                v += __shfl_down_sync(0xFFFFFFFFu, v, off);
            if (lane == 0) atomicAdd(&s_psum[j], v);
        }
        __syncthreads();
        if (tid < PPB) {
            const int c = (blockIdx.x * PPB + tid) & (CC - 1);
            atomicAdd(&g_chsum[TI][c], s_psum[tid]);
        }
    }
}

extern "C" void kernel_launch(void* const* d_in, const int* in_sizes, int n_in,
                              void* d_out, int out_size)
{
    const float* xe = (const float*)d_in[0];  // x_exc  [T,B,C,H,W]
    const float* xi = (const float*)d_in[1];  // x_inh  [T,B,C,H,W]
    const float* ar = (const float*)d_in[2];  // alpha_raw scalar
    const float* br = (const float*)d_in[3];  // beta_raw scalar
    float* out = (float*)d_out;               // spikes [T,B,C,H,W]

    lif_init<<<1, (T_STEPS - 1) * CC>>>();
    lif_step<0><<<NBLK, 256>>>(xe, xi, ar, br, out);
    lif_step<1><<<NBLK, 256>>>(xe, xi, ar, br, out);
    lif_step<2><<<NBLK, 256>>>(xe, xi, ar, br, out);
    lif_step<3><<<NBLK, 256>>>(xe, xi, ar, br, out);
    lif_step<4><<<NBLK, 256>>>(xe, xi, ar, br, out);
}

// round 6
// speedup vs baseline: 1.1757x; 1.1757x over previous
#include <cuda_runtime.h>
#include <cstdint>

// Problem shape (fixed by the reference)
#define T_STEPS 5
#define BB 32
#define CC 128
#define HW 1024                   // 32*32
#define NPT (BB * CC * HW)        // 4,194,304 elements per timestep
#define N4  (NPT / 4)             // 1,048,576 float4 positions per timestep

#define NBLK 608                  // 4 blocks/SM * 152 SMs (wave-1 resident; no churn)
#define NTHR 256

static constexpr float V_TH    = 0.5f;
static constexpr float W_DEC   = 0.5f;
static constexpr float LOWER_C = 0.2f - 0.03f;   // 0.17
static constexpr float UPPER_C = 0.2f + 0.03f;   // 0.23
static constexpr float EMA0    = 0.17f;
static constexpr float INV_N   = 1.0f / 32768.0f; // 1/(B*H*W)

// Cross-kernel state (device globals — no allocation allowed)
__device__ float g_mem[NPT];                 // membrane carry (L2-resident working set)
__device__ float g_chsum[T_STEPS - 1][CC];   // per-step per-channel spike sums

__device__ __forceinline__ float sigmoidf(float x) {
    return 1.0f / (1.0f + expf(-x));
}

__global__ void lif_init() {
    int i = threadIdx.x;
    if (i < (T_STEPS - 1) * CC) ((float*)g_chsum)[i] = 0.0f;
}

// One timestep: resident grid-stride loop with 2-stage software pipeline.
// - Warp covers 128 contiguous elements -> channel uniform per (warp, iter).
// - bw = beta*(1-inhw) per channel from smem table (EMA recurrence replayed
//   per block from persisted per-step sums; kernel boundary orders atomics).
// - Next iteration's loads issued before current iteration's compute -> two
//   load batches always in flight per thread (continuous DRAM issue).
template <int TI>
__global__ __launch_bounds__(NTHR)
void lif_step(const float* __restrict__ xe,
              const float* __restrict__ xi,
              const float* __restrict__ alpha_raw,
              const float* __restrict__ beta_raw,
              float* __restrict__ out)
{
    constexpr bool FIRST = (TI == 0);
    constexpr bool LAST  = (TI == T_STEPS - 1);

    __shared__ float s_bw[CC];
    __shared__ float s_cnt[CC];

    const int tid  = threadIdx.x;
    const int lane = tid & 31;

    const float beta  = sigmoidf(__ldg(beta_raw));
    const float alpha = 4.0f * sigmoidf(__ldg(alpha_raw));

    if (tid < CC) {
        float bw;
        if (FIRST) {
            bw = beta;                               // inhw starts at 0
        } else {
            float e = EMA0;
            #pragma unroll
            for (int k = 0; k < TI; ++k)
                e = 0.9f * e + 0.1f * (__ldcg(&g_chsum[k][tid]) * INV_N);
            const float inhw = 4.0f * (sigmoidf(LOWER_C - e) - sigmoidf(e - UPPER_C));
            bw = beta * (1.0f - inhw);
        }
        s_bw[tid] = bw;
        if (!LAST) s_cnt[tid] = 0.0f;
    }
    __syncthreads();

    const float4* xe4  = reinterpret_cast<const float4*>(xe)  + (size_t)TI * N4;
    const float4* xi4  = reinterpret_cast<const float4*>(xi)  + (size_t)TI * N4;
    float4*       out4 = reinterpret_cast<float4*>(out)       + (size_t)TI * N4;
    float4*       mem4 = reinterpret_cast<float4*>(g_mem);

    const int gsz = NBLK * NTHR;                     // 155,648 threads
    int i = blockIdx.x * NTHR + tid;                 // float4 index (< N4 always)

    // Prologue: load batch for first iteration
    float4 e4 = __ldcs(xe4 + i);
    float4 v4 = __ldcs(xi4 + i);
    float4 m4;
    if (FIRST) m4 = make_float4(0.f, 0.f, 0.f, 0.f);
    else       m4 = __ldcg(mem4 + i);

    while (true) {
        // Issue next iteration's loads BEFORE this iteration's compute
        const int inext = i + gsz;
        const bool more = inext < N4;
        float4 e4n, v4n, m4n;
        if (more) {
            e4n = __ldcs(xe4 + inext);
            v4n = __ldcs(xi4 + inext);
            if (!FIRST) m4n = __ldcg(mem4 + inext);
        }

        // ---- compute current iteration ----
        const int c = (i >> 8) & (CC - 1);           // channel (warp-uniform)
        const float bw = s_bw[c];
        float4 s;

        m4.x = W_DEC * m4.x + e4.x / (1.0f + alpha * v4.x) - bw * v4.x;
        s.x = (m4.x >= V_TH) ? 1.0f : 0.0f;  m4.x -= V_TH * s.x;
        m4.y = W_DEC * m4.y + e4.y / (1.0f + alpha * v4.y) - bw * v4.y;
        s.y = (m4.y >= V_TH) ? 1.0f : 0.0f;  m4.y -= V_TH * s.y;
        m4.z = W_DEC * m4.z + e4.z / (1.0f + alpha * v4.z) - bw * v4.z;
        s.z = (m4.z >= V_TH) ? 1.0f : 0.0f;  m4.z -= V_TH * s.z;
        m4.w = W_DEC * m4.w + e4.w / (1.0f + alpha * v4.w) - bw * v4.w;
        s.w = (m4.w >= V_TH) ? 1.0f : 0.0f;  m4.w -= V_TH * s.w;

        __stcs(out4 + i, s);
        if (!LAST) {
            __stcg(mem4 + i, m4);
            // Per-(warp,iter) spike count (integer-valued: exact in fp32)
            float cnt = s.x + s.y + s.z + s.w;
            #pragma unroll
            for (int off = 16; off > 0; off >>= 1)
                cnt += __shfl_down_sync(0xFFFFFFFFu, cnt, off);
            if (lane == 0) atomicAdd(&s_cnt[c], cnt);
        }

        if (!more) break;
        i = inext;
        e4 = e4n; v4 = v4n;
        if (FIRST) m4 = make_float4(0.f, 0.f, 0.f, 0.f);
        else       m4 = m4n;
    }

    if (!LAST) {
        __syncthreads();
        if (tid < CC) {
            const float v = s_cnt[tid];
            if (v != 0.0f) atomicAdd(&g_chsum[TI][tid], v);
        }
    }
}

extern "C" void kernel_launch(void* const* d_in, const int* in_sizes, int n_in,
                              void* d_out, int out_size)
{
    const float* xe = (const float*)d_in[0];  // x_exc  [T,B,C,H,W]
    const float* xi = (const float*)d_in[1];  // x_inh  [T,B,C,H,W]
    const float* ar = (const float*)d_in[2];  // alpha_raw scalar
    const float* br = (const float*)d_in[3];  // beta_raw scalar
    float* out = (float*)d_out;               // spikes [T,B,C,H,W]

    lif_init<<<1, (T_STEPS - 1) * CC>>>();
    lif_step<0><<<NBLK, NTHR>>>(xe, xi, ar, br, out);
    lif_step<1><<<NBLK, NTHR>>>(xe, xi, ar, br, out);
    lif_step<2><<<NBLK, NTHR>>>(xe, xi, ar, br, out);
    lif_step<3><<<NBLK, NTHR>>>(xe, xi, ar, br, out);
    lif_step<4><<<NBLK, NTHR>>>(xe, xi, ar, br, out);
}

// round 7
// speedup vs baseline: 1.5299x; 1.3013x over previous
#include <cuda_runtime.h>
#include <cstdint>

// Problem shape (fixed by the reference)
#define T_STEPS 5
#define BB 32
#define CC 128
#define HW 1024                    // 32*32
#define NPT (BB * CC * HW)         // 4,194,304 elements per timestep
#define N4  (NPT / 4)              // 1,048,576 float4 per timestep
#define NTHR 1024                  // threads per CTA (one CTA per channel)
#define BATCH_F4 (CC * HW / 4)     // 32768 float4 per batch slice
#define JSTRIDE  (4 * BATCH_F4)    // 131072: float4 stride between j-iterations
#define SMEM_BYTES (BB * HW * sizeof(float))   // 131072 B membrane carry

static constexpr float V_TH    = 0.5f;
static constexpr float W_DEC   = 0.5f;
static constexpr float LOWER_C = 0.2f - 0.03f;   // 0.17
static constexpr float UPPER_C = 0.2f + 0.03f;   // 0.23
static constexpr float EMA0    = 0.17f;
static constexpr float INV_N   = 1.0f / 32768.0f; // 1/(B*H*W)

__device__ __forceinline__ float sigmoidf(float x) {
    return 1.0f / (1.0f + expf(-x));
}

// One timestep for one channel, fully unrolled (8 iterations x 1024 threads x
// float4 covers the channel's 32 planes). mem carry is in SMEM, strictly
// thread-private slots -> no sync needed for it. 2-stage load pipeline.
template <bool FIRST, bool LAST>
__device__ __forceinline__ void do_step(
    const float4* __restrict__ xet, const float4* __restrict__ xit,
    float4* __restrict__ st, float4* __restrict__ s_mem,
    int g0, int tid, float alpha, float bw, float* s_wsum, float* cnt_out)
{
    float cnt = 0.0f;
    float4 e = __ldcs(xet + g0);
    float4 v = __ldcs(xit + g0);

    #pragma unroll
    for (int j = 0; j < 8; ++j) {
        float4 en, vn;
        if (j < 7) {                      // issue next loads before compute
            en = __ldcs(xet + g0 + (j + 1) * JSTRIDE);
            vn = __ldcs(xit + g0 + (j + 1) * JSTRIDE);
        }
        float4 m;
        if (FIRST) m = make_float4(0.f, 0.f, 0.f, 0.f);
        else       m = s_mem[j * NTHR + tid];
        float4 s;

        m.x = W_DEC * m.x + e.x / (1.0f + alpha * v.x) - bw * v.x;
        s.x = (m.x >= V_TH) ? 1.0f : 0.0f;  m.x -= V_TH * s.x;
        m.y = W_DEC * m.y + e.y / (1.0f + alpha * v.y) - bw * v.y;
        s.y = (m.y >= V_TH) ? 1.0f : 0.0f;  m.y -= V_TH * s.y;
        m.z = W_DEC * m.z + e.z / (1.0f + alpha * v.z) - bw * v.z;
        s.z = (m.z >= V_TH) ? 1.0f : 0.0f;  m.z -= V_TH * s.z;
        m.w = W_DEC * m.w + e.w / (1.0f + alpha * v.w) - bw * v.w;
        s.w = (m.w >= V_TH) ? 1.0f : 0.0f;  m.w -= V_TH * s.w;

        __stcs(st + g0 + j * JSTRIDE, s);
        if (!LAST) {
            s_mem[j * NTHR + tid] = m;
            cnt += s.x + s.y + s.z + s.w;
        }
        e = en; v = vn;
    }
    *cnt_out = cnt;
}

// One CTA per channel. The whole recurrence (mem carry, spike sums, EMA,
// inhibition weight) is channel-local, so no cross-CTA communication exists.
__global__ __launch_bounds__(NTHR, 1)
void lif_all(const float* __restrict__ xe,
             const float* __restrict__ xi,
             const float* __restrict__ alpha_raw,
             const float* __restrict__ beta_raw,
             float* __restrict__ out)
{
    extern __shared__ float4 s_mem[];          // 131 KB membrane carry
    __shared__ float s_wsum[NTHR / 32];
    __shared__ float s_bw;

    const int c    = blockIdx.x;               // channel
    const int tid  = threadIdx.x;
    const int lane = tid & 31;
    const int wid  = tid >> 5;

    const float alpha = 4.0f * sigmoidf(__ldg(alpha_raw));
    const float beta  = sigmoidf(__ldg(beta_raw));

    // Thread's base float4 index for j=0: batch (tid>>8), channel c, offset tid&255
    const int g0 = (tid >> 8) * BATCH_F4 + c * (HW / 4) + (tid & 255);

    const float4* xe4  = reinterpret_cast<const float4*>(xe);
    const float4* xi4  = reinterpret_cast<const float4*>(xi);
    float4*       out4 = reinterpret_cast<float4*>(out);

    float ema = EMA0;                          // maintained by thread 0 only
    float bw  = beta;                          // inhw starts at 0

    #pragma unroll
    for (int t = 0; t < T_STEPS; ++t) {
        const float4* xet = xe4  + (size_t)t * N4;
        const float4* xit = xi4  + (size_t)t * N4;
        float4*       st  = out4 + (size_t)t * N4;

        float cnt;
        if (t == 0)
            do_step<true, false>(xet, xit, st, s_mem, g0, tid, alpha, bw, s_wsum, &cnt);
        else if (t == T_STEPS - 1)
            do_step<false, true>(xet, xit, st, s_mem, g0, tid, alpha, bw, s_wsum, &cnt);
        else
            do_step<false, false>(xet, xit, st, s_mem, g0, tid, alpha, bw, s_wsum, &cnt);

        if (t < T_STEPS - 1) {
            // Block reduction of this channel's spike count (integer-valued
            // floats < 2^24: exact regardless of order)
            #pragma unroll
            for (int off = 16; off > 0; off >>= 1)
                cnt += __shfl_down_sync(0xFFFFFFFFu, cnt, off);
            if (lane == 0) s_wsum[wid] = cnt;
            __syncthreads();
            if (wid == 0) {
                float v = s_wsum[lane];        // exactly 32 warps
                #pragma unroll
                for (int off = 16; off > 0; off >>= 1)
                    v += __shfl_down_sync(0xFFFFFFFFu, v, off);
                if (lane == 0) {
                    ema = 0.9f * ema + 0.1f * (v * INV_N);
                    const float inhw =
                        4.0f * (sigmoidf(LOWER_C - ema) - sigmoidf(ema - UPPER_C));
                    s_bw = beta * (1.0f - inhw);
                }
            }
            __syncthreads();
            bw = s_bw;
        }
    }
}

extern "C" void kernel_launch(void* const* d_in, const int* in_sizes, int n_in,
                              void* d_out, int out_size)
{
    const float* xe = (const float*)d_in[0];  // x_exc  [T,B,C,H,W]
    const float* xi = (const float*)d_in[1];  // x_inh  [T,B,C,H,W]
    const float* ar = (const float*)d_in[2];  // alpha_raw scalar
    const float* br = (const float*)d_in[3];  // beta_raw scalar
    float* out = (float*)d_out;               // spikes [T,B,C,H,W]

    static bool attr_set = false;
    if (!attr_set) {
        cudaFuncSetAttribute(lif_all, cudaFuncAttributeMaxDynamicSharedMemorySize,
                             SMEM_BYTES);
        attr_set = true;
    }
    lif_all<<<CC, NTHR, SMEM_BYTES>>>(xe, xi, ar, br, out);
}